// round 15
// baseline (speedup 1.0000x reference)
#include <cuda_runtime.h>
#include <cstdint>

// LSTM T=8192, H=128. Cluster of 2 CTAs x 256 threads — PARTIAL-SUM EXCHANGE.
// CTA q owns h elements [q*64, q*64+64). Each thread (gate=r&3, m=r>>2) handles
// TWO rows: own row (gate*128 + q*64 + m) and peer row (gate*128 + peer*64 + m),
// both using ONLY local h columns [q*64, +64). Per step:
//   peer-row partial -> pack pairs (shfl.xor 1) -> st.async b64 to peer slot
//   own-row partial (h reused from regs) -> wait peer partials -> gpre = own+recv
// h NEVER crosses the fabric; the post-wait FMA block is gone.
// Local h: smem + 1 __syncthreads. tx barriers ping-pong, expect_tx = 1024 B.

#define HD 128
#define TPC 256
#define HALF 64

typedef unsigned long long u64;

__device__ __forceinline__ u64 ffma2(u64 a, u64 b, u64 c) {
    u64 d;
    asm("fma.rn.f32x2 %0, %1, %2, %3;" : "=l"(d) : "l"(a), "l"(b), "l"(c));
    return d;
}
__device__ __forceinline__ u64 addf2(u64 a, u64 b) {
    u64 d;
    asm("add.rn.f32x2 %0, %1, %2;" : "=l"(d) : "l"(a), "l"(b));
    return d;
}
__device__ __forceinline__ u64 pack2(float lo, float hi) {
    u64 r;
    asm("mov.b64 %0, {%1, %2};" : "=l"(r) : "f"(lo), "f"(hi));
    return r;
}
__device__ __forceinline__ void unpack2(u64 v, float& lo, float& hi) {
    asm("mov.b64 {%0, %1}, %2;" : "=f"(lo), "=f"(hi) : "l"(v));
}
__device__ __forceinline__ float tanhfast(float x) {
    float y;
    asm("tanh.approx.f32 %0, %1;" : "=f"(y) : "f"(x));
    return y;
}
__device__ __forceinline__ uint32_t smem_u32(const void* p) {
    return (uint32_t)__cvta_generic_to_shared(p);
}
__device__ __forceinline__ uint32_t mapa_u32(uint32_t addr, uint32_t rank) {
    uint32_t r;
    asm("mapa.shared::cluster.u32 %0, %1, %2;" : "=r"(r) : "r"(addr), "r"(rank));
    return r;
}
__device__ __forceinline__ void mbar_init(uint32_t a, uint32_t cnt) {
    asm volatile("mbarrier.init.shared.b64 [%0], %1;" :: "r"(a), "r"(cnt) : "memory");
}
__device__ __forceinline__ void mbar_arrive_expect_tx(uint32_t a, uint32_t tx) {
    asm volatile("mbarrier.arrive.expect_tx.shared.b64 _, [%0], %1;"
                 :: "r"(a), "r"(tx) : "memory");
}
__device__ __forceinline__ void st_async_f32(uint32_t raddr, float v, uint32_t rmbar) {
    asm volatile(
        "st.async.shared::cluster.mbarrier::complete_tx::bytes.f32 [%0], %1, [%2];"
        :: "r"(raddr), "f"(v), "r"(rmbar) : "memory");
}
__device__ __forceinline__ void st_async_b64(uint32_t raddr, u64 v, uint32_t rmbar) {
    asm volatile(
        "st.async.shared::cluster.mbarrier::complete_tx::bytes.b64 [%0], %1, [%2];"
        :: "r"(raddr), "l"(v), "r"(rmbar) : "memory");
}
__device__ __forceinline__ void mbar_wait(uint32_t a, uint32_t parity) {
    asm volatile(
        "{\n\t"
        ".reg .pred P;\n\t"
        "WL_%=:\n\t"
        "mbarrier.try_wait.parity.acquire.cluster.shared::cta.b64 P, [%0], %1;\n\t"
        "@P bra WD_%=;\n\t"
        "bra WL_%=;\n\t"
        "WD_%=:\n\t"
        "}" :: "r"(a), "r"(parity) : "memory");
}
__device__ __forceinline__ void cluster_sync() {
    asm volatile("barrier.cluster.arrive.aligned;" ::: "memory");
    asm volatile("barrier.cluster.wait.aligned;" ::: "memory");
}

extern "C" __global__ void __launch_bounds__(TPC, 1) __cluster_dims__(2, 1, 1)
lstm_partial_kernel(const float* __restrict__ x,
                    const float* __restrict__ W_ih,
                    const float* __restrict__ W_hh,
                    const float* __restrict__ b_ih,
                    const float* __restrict__ b_hh,
                    const float* __restrict__ W_lin,
                    const float* __restrict__ b_lin,
                    const float* __restrict__ h0,
                    const float* __restrict__ c0,
                    float* __restrict__ out,
                    int T) {
    __shared__ __align__(16) float hs[2][HALF];     // own h half, double-buffered
    __shared__ __align__(16) float precv[2][TPC];   // received peer partials
    __shared__ __align__(16) float hfin[HALF];      // CTA0: peer's final h half
    __shared__ float red[8];
    __shared__ __align__(8) u64 mbar[2];
    __shared__ __align__(8) u64 mbfin;

    const int r = threadIdx.x;
    uint32_t rank;
    asm("mov.u32 %0, %%cluster_ctarank;" : "=r"(rank));
    const int q = (int)rank;
    const int peer = 1 - q;
    const int gate = r & 3;           // i,f,g,o
    const int m    = r >> 2;          // element index within own half, 0..63
    const int own_row  = gate * HD + q * HALF + m;
    const int peer_row = gate * HD + peer * HALF + m;
    const bool prod = (gate == 0);

    const float in_sc  = (gate == 2) ? 1.f  : 0.5f;
    const float out_sc = (gate == 2) ? 1.f  : 0.5f;
    const float out_b  = (gate == 2) ? 0.f  : 0.5f;

    const uint32_t mb0 = smem_u32(&mbar[0]);
    const uint32_t mb1 = smem_u32(&mbar[1]);
    const uint32_t mbf = smem_u32(&mbfin);
    const uint32_t peer_mb0 = mapa_u32(mb0, (uint32_t)peer);
    const uint32_t peer_mb1 = mapa_u32(mb1, (uint32_t)peer);
    const uint32_t peer_pr  = mapa_u32(smem_u32(&precv[0][0]), (uint32_t)peer);
    const uint32_t cta0_hfin = mapa_u32(smem_u32(&hfin[0]), 0u);
    const uint32_t cta0_mbf  = mapa_u32(mbf, 0u);

    if (r == 0) {
        mbar_init(mb0, 1); mbar_init(mb1, 1); mbar_init(mbf, 1);
        mbar_arrive_expect_tx(mb0, 1024);   // step 0 partials
        mbar_arrive_expect_tx(mb1, 1024);   // step 1 partials
        mbar_arrive_expect_tx(mbf, 256);    // final h half (CTA0 receives)
    }

    if (r < HALF) hs[0][r] = h0[q * HALF + r];
    float c = prod ? c0[q * HALF + m] : 0.f;

    // weights: both rows over LOCAL columns [q*64, q*64+64)
    const float wih  = W_ih[own_row];
    const float bsum = b_ih[own_row] + b_hh[own_row];
    u64 wown[32], wpeer[32];
    {
        const u64* wo = (const u64*)(W_hh + (size_t)own_row * HD + q * HALF);
        const u64* wp = (const u64*)(W_hh + (size_t)peer_row * HD + q * HALF);
        #pragma unroll
        for (int k = 0; k < 32; ++k) wown[k]  = wo[k];
        #pragma unroll
        for (int k = 0; k < 32; ++k) wpeer[k] = wp[k];
    }
    __syncthreads();
    cluster_sync();     // all barriers armed + hs[0] visible before any st.async

    float xt = __ldg(&x[0]);

    for (int t = 0; t < T; ++t) {
        const int b  = t & 1;
        const int nb = b ^ 1;
        const uint32_t mbw  = b ? mb1 : mb0;
        const uint32_t psnd = b ? peer_mb1 : peer_mb0;   // same-step barrier
        const uint32_t parity = (uint32_t)((t >> 1) & 1);

        const float xnext = __ldg(&x[(t + 1 < T) ? (t + 1) : t]);

        // load local h half once (16 LDS.128), reuse for both rows
        ulonglong2 hr[16];
        {
            const ulonglong2* hv2 = (const ulonglong2*)(&hs[b][0]);
            #pragma unroll
            for (int k = 0; k < 16; ++k) hr[k] = hv2[k];
        }

        // ---- peer-row partial (ships out ASAP) ----
        u64 p0 = 0ull, p1 = 0ull, p2 = 0ull, p3 = 0ull;
        #pragma unroll
        for (int k = 0; k < 16; k += 2) {
            p0 = ffma2(wpeer[2 * k + 0], hr[k].x, p0);
            p1 = ffma2(wpeer[2 * k + 1], hr[k].y, p1);
            p2 = ffma2(wpeer[2 * k + 2], hr[k + 1].x, p2);
            p3 = ffma2(wpeer[2 * k + 3], hr[k + 1].y, p3);
        }
        float pp;
        {
            const u64 sv = addf2(addf2(p0, p1), addf2(p2, p3));
            float lo, hi;
            unpack2(sv, lo, hi);
            pp = lo + hi;
        }
        // pack gate-pairs: even-gate lanes send (pp_g, pp_{g+1}) as one b64.
        const float pp_n = __shfl_xor_sync(0xFFFFFFFFu, pp, 1);
        if ((gate & 1) == 0) {
            const u64 msg = pack2(pp, pp_n);
            const uint32_t slot = (uint32_t)(b * TPC + 4 * m + gate);
            st_async_b64(peer_pr + slot * 4u, msg, psnd);
        }

        // ---- own-row partial (h already in registers) ----
        u64 a0 = pack2(fmaf(wih, xt, bsum), 0.f);
        u64 a1 = 0ull, a2 = 0ull, a3 = 0ull;
        #pragma unroll
        for (int k = 0; k < 16; k += 2) {
            a0 = ffma2(wown[2 * k + 0], hr[k].x, a0);
            a1 = ffma2(wown[2 * k + 1], hr[k].y, a1);
            a2 = ffma2(wown[2 * k + 2], hr[k + 1].x, a2);
            a3 = ffma2(wown[2 * k + 3], hr[k + 1].y, a3);
        }
        float po;
        {
            const u64 sv = addf2(addf2(a0, a1), addf2(a2, a3));
            float lo, hi;
            unpack2(sv, lo, hi);
            po = lo + hi;
        }

        mbar_wait(mbw, parity);                        // peer partials landed
        if (r == 0) mbar_arrive_expect_tx(mbw, 1024);  // re-arm for step t+2

        const float gpre = po + precv[b][r];

        const float act = fmaf(out_sc, tanhfast(in_sc * gpre), out_b);

        const float fv = __shfl_xor_sync(0xFFFFFFFFu, act, 1);
        const float gv = __shfl_xor_sync(0xFFFFFFFFu, act, 2);
        const float ov = __shfl_xor_sync(0xFFFFFFFFu, act, 3);

        if (prod) {
            c = fmaf(fv, c, act * gv);           // act == i on producer lane
            const float hnew = ov * tanhfast(c);
            hs[nb][m] = hnew;                    // local only — no remote h!
        }
        __syncthreads();
        xt = xnext;
    }

    const int bf = T & 1;

    // CTA1 ships its final h half to CTA0
    if (q == 1 && r < HALF) {
        st_async_f32(cta0_hfin + (uint32_t)(r * 4), hs[bf][r], cta0_mbf);
    }

    if (q == 0) {
        mbar_wait(mbf, 0);
        float v = 0.f;
        if (r < HD) {
            const float hv = (r < HALF) ? hs[bf][r] : hfin[r - HALF];
            v = hv * W_lin[r];
        }
        #pragma unroll
        for (int o = 16; o > 0; o >>= 1)
            v += __shfl_down_sync(0xFFFFFFFFu, v, o);
        if ((r & 31) == 0) red[r >> 5] = v;
        __syncthreads();
        if (r == 0) out[0] = red[0] + red[1] + red[2] + red[3] + b_lin[0];
    }
    cluster_sync();   // both CTAs outlive all in-flight st.async
}

extern "C" void kernel_launch(void* const* d_in, const int* in_sizes, int n_in,
                              void* d_out, int out_size) {
    const float* x     = (const float*)d_in[0];
    const float* W_ih  = (const float*)d_in[1];
    const float* W_hh  = (const float*)d_in[2];
    const float* b_ih  = (const float*)d_in[3];
    const float* b_hh  = (const float*)d_in[4];
    const float* W_lin = (const float*)d_in[5];
    const float* b_lin = (const float*)d_in[6];
    const float* h0    = (const float*)d_in[7];
    const float* c0    = (const float*)d_in[8];
    float* out = (float*)d_out;

    const int T = in_sizes[0];

    lstm_partial_kernel<<<2, TPC>>>(x, W_ih, W_hh, b_ih, b_hh,
                                    W_lin, b_lin, h0, c0, out, T);
}

// round 16
// speedup vs baseline: 1.0646x; 1.0646x over previous
#include <cuda_runtime.h>
#include <cstdint>

// LSTM T=8192, H=128. Cluster of 2 CTAs x 256 threads (R7 champion skeleton).
// All W_hh in registers. Interleaved lanes: gate=r&3, element m=r>>2; gate
// combine via 3 shfl.bfly. Local h via smem + one __syncthreads.
// R16 change vs R7: remote h sends PAIRED — even-m producer lanes gather the
// m+1 neighbor's hnew via shfl.xor(4) (producer lanes are 4 apart) and issue
// ONE st.async.b64 per pair: 32 fabric messages/step instead of 64,
// expect_tx unchanged (256 B).

#define HD 128
#define TPC 256
#define HALF 64

typedef unsigned long long u64;

__device__ __forceinline__ u64 ffma2(u64 a, u64 b, u64 c) {
    u64 d;
    asm("fma.rn.f32x2 %0, %1, %2, %3;" : "=l"(d) : "l"(a), "l"(b), "l"(c));
    return d;
}
__device__ __forceinline__ u64 addf2(u64 a, u64 b) {
    u64 d;
    asm("add.rn.f32x2 %0, %1, %2;" : "=l"(d) : "l"(a), "l"(b));
    return d;
}
__device__ __forceinline__ u64 pack2(float lo, float hi) {
    u64 r;
    asm("mov.b64 %0, {%1, %2};" : "=l"(r) : "f"(lo), "f"(hi));
    return r;
}
__device__ __forceinline__ void unpack2(u64 v, float& lo, float& hi) {
    asm("mov.b64 {%0, %1}, %2;" : "=f"(lo), "=f"(hi) : "l"(v));
}
__device__ __forceinline__ float tanhfast(float x) {
    float y;
    asm("tanh.approx.f32 %0, %1;" : "=f"(y) : "f"(x));
    return y;
}
__device__ __forceinline__ uint32_t smem_u32(const void* p) {
    return (uint32_t)__cvta_generic_to_shared(p);
}
__device__ __forceinline__ uint32_t mapa_u32(uint32_t addr, uint32_t rank) {
    uint32_t r;
    asm("mapa.shared::cluster.u32 %0, %1, %2;" : "=r"(r) : "r"(addr), "r"(rank));
    return r;
}
__device__ __forceinline__ void mbar_init(uint32_t a, uint32_t cnt) {
    asm volatile("mbarrier.init.shared.b64 [%0], %1;" :: "r"(a), "r"(cnt) : "memory");
}
__device__ __forceinline__ void mbar_arrive(uint32_t a) {
    asm volatile("mbarrier.arrive.shared.b64 _, [%0];" :: "r"(a) : "memory");
}
__device__ __forceinline__ void mbar_arrive_expect_tx(uint32_t a, uint32_t tx) {
    asm volatile("mbarrier.arrive.expect_tx.shared.b64 _, [%0], %1;"
                 :: "r"(a), "r"(tx) : "memory");
}
__device__ __forceinline__ void st_async_b64(uint32_t raddr, u64 v, uint32_t rmbar) {
    asm volatile(
        "st.async.shared::cluster.mbarrier::complete_tx::bytes.b64 [%0], %1, [%2];"
        :: "r"(raddr), "l"(v), "r"(rmbar) : "memory");
}
__device__ __forceinline__ void mbar_wait(uint32_t a, uint32_t parity) {
    asm volatile(
        "{\n\t"
        ".reg .pred P;\n\t"
        "WL_%=:\n\t"
        "mbarrier.try_wait.parity.acquire.cluster.shared::cta.b64 P, [%0], %1;\n\t"
        "@P bra WD_%=;\n\t"
        "bra WL_%=;\n\t"
        "WD_%=:\n\t"
        "}" :: "r"(a), "r"(parity) : "memory");
}
__device__ __forceinline__ void cluster_sync() {
    asm volatile("barrier.cluster.arrive.aligned;" ::: "memory");
    asm volatile("barrier.cluster.wait.aligned;" ::: "memory");
}

extern "C" __global__ void __launch_bounds__(TPC, 1) __cluster_dims__(2, 1, 1)
lstm_cluster_kernel(const float* __restrict__ x,
                    const float* __restrict__ W_ih,
                    const float* __restrict__ W_hh,
                    const float* __restrict__ b_ih,
                    const float* __restrict__ b_hh,
                    const float* __restrict__ W_lin,
                    const float* __restrict__ b_lin,
                    const float* __restrict__ h0,
                    const float* __restrict__ c0,
                    float* __restrict__ out,
                    int T) {
    __shared__ __align__(16) float hs[2][HD];
    __shared__ float red[8];
    __shared__ __align__(8) u64 mbar[2];

    const int r = threadIdx.x;
    uint32_t rank;
    asm("mov.u32 %0, %%cluster_ctarank;" : "=r"(rank));
    const int q = (int)rank;
    const int peer = 1 - q;
    const int gate = r & 3;           // i,f,g,o interleaved within warp
    const int m    = r >> 2;          // local element 0..63
    const int row  = gate * HD + q * HALF + m;
    const int j    = q * HALF + m;
    const bool prod = (gate == 0);
    const bool sender = prod && ((m & 1) == 0);   // even-m producers send pairs

    // act = out_sc * tanh(in_sc * x) + out_b
    //   sigmoid gates (i,f,o): 0.5*tanh(0.5x)+0.5 ; g gate: tanh(x)
    const float in_sc  = (gate == 2) ? 1.f  : 0.5f;
    const float out_sc = (gate == 2) ? 1.f  : 0.5f;
    const float out_b  = (gate == 2) ? 0.f  : 0.5f;

    const uint32_t mb0 = smem_u32(&mbar[0]);
    const uint32_t mb1 = smem_u32(&mbar[1]);
    const uint32_t peer_mb0 = mapa_u32(mb0, (uint32_t)peer);
    const uint32_t peer_mb1 = mapa_u32(mb1, (uint32_t)peer);
    const uint32_t peer_hs  = mapa_u32(smem_u32(&hs[0][0]), (uint32_t)peer);

    if (r == 0) { mbar_init(mb0, 1); mbar_init(mb1, 1); }

    if (r < HD) hs[0][r] = h0[r];
    float c = prod ? c0[j] : 0.f;

    const float wih  = W_ih[row];
    const float bsum = b_ih[row] + b_hh[row];
    u64 wl[32], wrm[32];
    {
        const u64* wrow = (const u64*)(W_hh + (size_t)row * HD);
        #pragma unroll
        for (int k = 0; k < 32; ++k) wl[k]  = wrow[q * 32 + k];
        #pragma unroll
        for (int k = 0; k < 32; ++k) wrm[k] = wrow[peer * 32 + k];
    }
    __syncthreads();
    if (r == 0) {
        mbar_arrive(mb0);                 // step 0 passes trivially (h0 local)
        mbar_arrive_expect_tx(mb1, 256);  // arm for step 1's incoming half
    }
    __syncthreads();
    cluster_sync();                       // peer barrier init/arm visible

    const int q16 = q * 16, p16 = peer * 16;
    float xt = __ldg(&x[0]);

    for (int t = 0; t < T; ++t) {
        const int b  = t & 1;
        const int nb = b ^ 1;
        const uint32_t mbw = b ? mb1 : mb0;
        const uint32_t pmb = nb ? peer_mb1 : peer_mb0;
        const uint32_t parity = (uint32_t)((t >> 1) & 1);

        const float xnext = __ldg(&x[(t + 1 < T) ? (t + 1) : t]);

        u64 a0 = pack2(fmaf(wih, xt, bsum), 0.f);
        u64 a1 = 0ull, a2 = 0ull, a3 = 0ull;

        const ulonglong2* hv2 = (const ulonglong2*)(&hs[b][0]);

        // local half (independent of peer)
        #pragma unroll
        for (int k = 0; k < 16; k += 2) {
            ulonglong2 u = hv2[q16 + k];
            ulonglong2 v = hv2[q16 + k + 1];
            a0 = ffma2(wl[2 * k + 0], u.x, a0);
            a1 = ffma2(wl[2 * k + 1], u.y, a1);
            a2 = ffma2(wl[2 * k + 2], v.x, a2);
            a3 = ffma2(wl[2 * k + 3], v.y, a3);
        }

        mbar_wait(mbw, parity);                       // peer half landed
        if (r == 0) mbar_arrive_expect_tx(mbw, 256);  // re-arm for step t+2

        #pragma unroll
        for (int k = 0; k < 16; k += 2) {
            ulonglong2 u = hv2[p16 + k];
            ulonglong2 v = hv2[p16 + k + 1];
            a0 = ffma2(wrm[2 * k + 0], u.x, a0);
            a1 = ffma2(wrm[2 * k + 1], u.y, a1);
            a2 = ffma2(wrm[2 * k + 2], v.x, a2);
            a3 = ffma2(wrm[2 * k + 3], v.y, a3);
        }

        // packed combine: (a0+a1) + (a2+a3), then one scalar add
        const u64 sv = addf2(addf2(a0, a1), addf2(a2, a3));
        float slo, shi;
        unpack2(sv, slo, shi);
        const float gpre = slo + shi;

        // MUFU tanh-based activation
        const float act = fmaf(out_sc, tanhfast(in_sc * gpre), out_b);

        const float fv = __shfl_xor_sync(0xFFFFFFFFu, act, 1);
        const float gv = __shfl_xor_sync(0xFFFFFFFFu, act, 2);
        const float ov = __shfl_xor_sync(0xFFFFFFFFu, act, 3);

        float hnew = 0.f;
        if (prod) {
            c = fmaf(fv, c, act * gv);           // act == i on producer lane
            hnew = ov * tanhfast(c);
            hs[nb][j] = hnew;                    // local via smem
        }
        // pair producers: even-m lane (4m) gathers (m+1)'s hnew from lane 4m+4
        const float hnb = __shfl_xor_sync(0xFFFFFFFFu, hnew, 4);
        if (sender) {
            const u64 msg = pack2(hnew, hnb);
            const uint32_t off = (uint32_t)((nb * HD + j) * 4);  // j even -> 8B aligned
            st_async_b64(peer_hs + off, msg, pmb);   // one message per pair
        }
        __syncthreads();
        xt = xnext;
    }

    // CTA0 consumes final h
    if (q == 0) {
        const uint32_t mbw = (T & 1) ? mb1 : mb0;
        mbar_wait(mbw, (uint32_t)((T >> 1) & 1));
        const int bf = T & 1;
        float v = (r < HD) ? hs[bf][r] * W_lin[r] : 0.f;
        #pragma unroll
        for (int o = 16; o > 0; o >>= 1)
            v += __shfl_down_sync(0xFFFFFFFFu, v, o);
        if ((r & 31) == 0) red[r >> 5] = v;
        __syncthreads();
        if (r == 0) out[0] = red[0] + red[1] + red[2] + red[3] + b_lin[0];
    }
    cluster_sync();   // peer must outlive CTA0's final consumption
}

extern "C" void kernel_launch(void* const* d_in, const int* in_sizes, int n_in,
                              void* d_out, int out_size) {
    const float* x     = (const float*)d_in[0];
    const float* W_ih  = (const float*)d_in[1];
    const float* W_hh  = (const float*)d_in[2];
    const float* b_ih  = (const float*)d_in[3];
    const float* b_hh  = (const float*)d_in[4];
    const float* W_lin = (const float*)d_in[5];
    const float* b_lin = (const float*)d_in[6];
    const float* h0    = (const float*)d_in[7];
    const float* c0    = (const float*)d_in[8];
    float* out = (float*)d_out;

    const int T = in_sizes[0];

    lstm_cluster_kernel<<<2, TPC>>>(x, W_ih, W_hh, b_ih, b_hh,
                                    W_lin, b_lin, h0, c0, out, T);
}